// round 12
// baseline (speedup 1.0000x reference)
#include <cuda_runtime.h>
#include <cuda_bf16.h>
#include <math.h>
#include <stdint.h>

#define Bz   128
#define Tz   1024
#define INz  256
#define Hz   512
#define G4   2048   // 4*H

// ---------------- scratch (device globals) ---------------------------------
__device__ __nv_bfloat16 g_xgb[(size_t)Bz * Tz * G4];   // gate preacts, bf16, PERMUTED cols
__device__ __nv_bfloat16 g_hsb[(size_t)Bz * Tz * Hz];   // layer-0 hidden outputs, bf16 plain
__device__ __nv_bfloat16 g_xb[(size_t)Bz * Tz * INz];   // x pre-converted to bf16
__device__ __nv_bfloat16 g_wb[G4 * Hz];                 // W_ih pre-converted to bf16
__device__ unsigned g_phb[2][4][8192];                  // h exchange, bf16 A-frag layout
__device__ float g_hlast[Bz * Hz];                      // final h of running layer
__device__ unsigned g_flag[4][32];                      // per-CTA progress flags

// ---------------------------------------------------------------------------
__device__ __forceinline__ void mma_bf16(float* d, const uint4& a, unsigned b0, unsigned b1) {
    asm volatile(
        "mma.sync.aligned.m16n8k16.row.col.f32.bf16.bf16.f32 "
        "{%0,%1,%2,%3}, {%4,%5,%6,%7}, {%8,%9}, {%0,%1,%2,%3};\n"
        : "+f"(d[0]), "+f"(d[1]), "+f"(d[2]), "+f"(d[3])
        : "r"(a.x), "r"(a.y), "r"(a.z), "r"(a.w), "r"(b0), "r"(b1));
}
__device__ __forceinline__ float tanha(float x) {
    float y; asm("tanh.approx.f32 %0, %1;" : "=f"(y) : "f"(x)); return y;
}
__device__ __forceinline__ float siga(float x) { return 0.5f * tanha(0.5f * x) + 0.5f; }
__device__ __forceinline__ unsigned pack_bf16x2(float x, float y) {
    __nv_bfloat162 v = __floats2bfloat162_rn(x, y);
    return *(unsigned*)&v;
}

// ---------------------------------------------------------------------------
__global__ void zero_state_kernel() {
    int i = blockIdx.x * blockDim.x + threadIdx.x;
    if (i < 2 * 4 * 8192) ((unsigned*)g_phb)[i] = 0u;
    else if (i < 2 * 4 * 8192 + 4 * 32) ((unsigned*)g_flag)[i - 2 * 4 * 8192] = 0u;
}

// fp32 -> bf16 bulk convert (4 elts/thread)
__global__ void conv_bf16_kernel(const float* __restrict__ src,
                                 __nv_bfloat16* __restrict__ dst, int n4) {
    int i = blockIdx.x * blockDim.x + threadIdx.x;
    if (i < n4) {
        float4 v = *(const float4*)(src + (size_t)i * 4);
        uint2 o;
        o.x = pack_bf16x2(v.x, v.y);
        o.y = pack_bf16x2(v.z, v.w);
        *(uint2*)(dst + (size_t)i * 4) = o;
    }
}

// ---------------------------------------------------------------------------
// Input GEMM, bf16 m16n8k16, bf16 A and B sources, bf16 output.
// BM=128, BN=64, BK=32, 256 thr (4m x 2n warps). Permuted gate-col output.
// ---------------------------------------------------------------------------
template <int K>
__global__ void __launch_bounds__(256) gemm_bf16_kernel(
    const __nv_bfloat16* __restrict__ Xb,
    const float* __restrict__ b1, const float* __restrict__ b2)
{
    __shared__ uint4 Abuf[8][2][32];   // [m16][k16 step][lane] 8KB
    __shared__ uint2 Bbuf[8][2][32];   // [n8][k16 step][lane]  2KB
    __shared__ float sbias[64];

    int tid = threadIdx.x, lane = tid & 31, warp = tid >> 5;
    int wm = warp & 3, wn = warp >> 2;
    int g = lane >> 2, tig = lane & 3;
    size_t m0g = (size_t)blockIdx.y * 128;
    int    n0g = blockIdx.x * 64;

    if (tid < 64) {
        int ng  = n0g + tid;
        int row = (ng & 3) * Hz + (ng >> 2);
        sbias[tid] = b1[row] + b2[row];
    }

    float d[2][4][4];
#pragma unroll
    for (int a = 0; a < 2; a++)
#pragma unroll
        for (int b = 0; b < 4; b++)
#pragma unroll
            for (int c = 0; c < 4; c++) d[a][b][c] = 0.0f;

    for (int kb = 0; kb < K; kb += 32) {
        // ---- A fill: 4 quads/thread ----
#pragma unroll
        for (int i = 0; i < 4; i++) {
            int f4 = tid * 4 + i;
            int m = f4 >> 3, q = f4 & 7;
            uint2 u = *(const uint2*)&Xb[(m0g + m) * K + kb + q * 4];
            int mt = m >> 4, gg = m & 7, odd = (m >> 3) & 1;
            int ks = q >> 2, kc = (q >> 1) & 1, tg2 = (q & 1) * 2;
            int e = odd + 2 * kc;
            ((unsigned*)&Abuf[mt][ks][gg * 4 + tg2])[e]     = u.x;
            ((unsigned*)&Abuf[mt][ks][gg * 4 + tg2 + 1])[e] = u.y;
        }
        // ---- B fill: 2 quads/thread (from pre-converted bf16 W) ----
#pragma unroll
        for (int i = 0; i < 2; i++) {
            int fb = tid * 2 + i;
            int n = fb >> 3, q = fb & 7;
            int row = ((n0g + n) & 3) * Hz + ((n0g + n) >> 2);
            uint2 u = *(const uint2*)&g_wb[(size_t)row * K + kb + q * 4];
            int nt = n >> 3, gb = n & 7;
            int ks = q >> 2, r = (q >> 1) & 1, tg = (q & 1) * 2;
            ((unsigned*)&Bbuf[nt][ks][gb * 4 + tg])[r]     = u.x;
            ((unsigned*)&Bbuf[nt][ks][gb * 4 + tg + 1])[r] = u.y;
        }
        __syncthreads();
#pragma unroll
        for (int ks = 0; ks < 2; ks++) {
            uint4 a0 = Abuf[wm * 2 + 0][ks][lane];
            uint4 a1 = Abuf[wm * 2 + 1][ks][lane];
#pragma unroll
            for (int j = 0; j < 4; j++) {
                uint2 bb = Bbuf[wn * 4 + j][ks][lane];
                mma_bf16(d[0][j], a0, bb.x, bb.y);
                mma_bf16(d[1][j], a1, bb.x, bb.y);
            }
        }
        __syncthreads();
    }

    // ---- epilogue: add bias, store bf16 permuted ----
#pragma unroll
    for (int mt = 0; mt < 2; mt++) {
#pragma unroll
        for (int j = 0; j < 4; j++) {
            int col = wn * 32 + j * 8 + 2 * tig;
            float bi0 = sbias[col], bi1 = sbias[col + 1];
            size_t m = m0g + wm * 32 + mt * 16 + g;
            unsigned v0 = pack_bf16x2(d[mt][j][0] + bi0, d[mt][j][1] + bi1);
            unsigned v1 = pack_bf16x2(d[mt][j][2] + bi0, d[mt][j][3] + bi1);
            *(unsigned*)&g_xgb[m * G4 + n0g + col]       = v0;
            *(unsigned*)&g_xgb[(m + 8) * G4 + n0g + col] = v1;
        }
    }
}

// ---------------------------------------------------------------------------
// Persistent recurrent kernel: 64 CTAs, each handles ONE col tile (16 hid
// cols) for TWO independent batch groups, interleaved. The second group's
// compute hides the first group's flag/L2 round-trip latency.
// W_hh fragments in registers (shared across both groups).
// Dynamic smem: Hsm 2x32KB + Hstage 1KB = 66.5 KB.
// ---------------------------------------------------------------------------
__global__ void __launch_bounds__(256, 1) lstm_seq2(
    const float* __restrict__ w_hh, int store_hs)
{
    extern __shared__ unsigned char smraw[];
    uint4* HsmB   = (uint4*)smraw;          // [grp(2)][mt(2)][ks(32)][lane(32)]
    uint4* Hstage = HsmB + 4096;            // [mt(2)][lane(32)]

    int tid = threadIdx.x, lane = tid & 31, warp = tid >> 5;
    int wm = warp & 1, wn = warp >> 1;
    int g = lane >> 2, tig = lane & 3;
    int ct = blockIdx.x & 31, pp = blockIdx.x >> 5;   // col tile, group pair
    int j0 = ct * 16;
    int bt0 = pp * 2;
    int odd = tig & 1;
    int rl  = wm * 16 + g + 8 * odd;

    // ---- W_hh fragments into registers (held for all 1024 steps) ----
    unsigned wreg[2][32][2];
#pragma unroll
    for (int nt = 0; nt < 2; nt++) {
        int nl  = (wn * 2 + nt) * 8 + g;
        int row = (nl & 3) * Hz + j0 + (nl >> 2);
        const float* wr = &w_hh[(size_t)row * Hz];
#pragma unroll
        for (int ks = 0; ks < 32; ks++) {
#pragma unroll
            for (int r = 0; r < 2; r++) {
                float2 wv = *(const float2*)&wr[ks * 16 + 8 * r + 2 * tig];
                wreg[nt][ks][r] = pack_bf16x2(wv.x, wv.y);
            }
        }
    }

    float cst[2][2] = {{0.0f, 0.0f}, {0.0f, 0.0f}};

#pragma unroll 1
    for (int t = 0; t < Tz; t++) {
        // ---- prefetch xg (bf16) for both groups ----
        uint2 xu[2][2];
#pragma unroll
        for (int grp = 0; grp < 2; grp++) {
            int b = (bt0 + grp) * 32 + rl;
#pragma unroll
            for (int nt = 0; nt < 2; nt++) {
                int jjloc = (wn * 2 + nt) * 2 + (tig >> 1);
                xu[grp][nt] = __ldcs((const uint2*)
                    &g_xgb[((size_t)b * Tz + t) * G4 + ct * 64 + jjloc * 4]);
            }
        }

#pragma unroll 1
        for (int grp = 0; grp < 2; grp++) {
            int bt = bt0 + grp;
            int b  = bt * 32 + rl;
            unsigned* flags = &g_flag[bt][0];
            uint4* bufR = (uint4*)&g_phb[t & 1][bt][0];
            uint4* bufW = (uint4*)&g_phb[(t & 1) ^ 1][bt][0];
            uint4* Hsm  = HsmB + grp * 2048;

            // ---- wait: all 32 CTAs of this group finished step t-1 ----
            if (warp == 0) {
                unsigned v;
                do {
                    asm volatile("ld.acquire.gpu.global.u32 %0, [%1];"
                                 : "=r"(v) : "l"(flags + lane) : "memory");
                } while (!__all_sync(0xffffffffu, (int)(v >= (unsigned)t)));
            }
            __syncthreads();

            // ---- copy h tile (frag layout): global -> smem ----
#pragma unroll
            for (int i = 0; i < 8; i++) {
                int idx = i * 256 + tid;
                Hsm[idx] = __ldcg(&bufR[idx]);
            }
            __syncthreads();

            // ---- mma: 4 accumulator chains (ks parity x nt) ----
            float dE0[4] = {0, 0, 0, 0}, dO0[4] = {0, 0, 0, 0};
            float dE1[4] = {0, 0, 0, 0}, dO1[4] = {0, 0, 0, 0};
#pragma unroll
            for (int ks = 0; ks < 32; ks += 2) {
                uint4 a0 = Hsm[(wm * 32 + ks) * 32 + lane];
                uint4 a1 = Hsm[(wm * 32 + ks + 1) * 32 + lane];
                mma_bf16(dE0, a0, wreg[0][ks][0],     wreg[0][ks][1]);
                mma_bf16(dE1, a0, wreg[1][ks][0],     wreg[1][ks][1]);
                mma_bf16(dO0, a1, wreg[0][ks + 1][0], wreg[0][ks + 1][1]);
                mma_bf16(dO1, a1, wreg[1][ks + 1][0], wreg[1][ks + 1][1]);
            }
            float d[2][4];
#pragma unroll
            for (int c = 0; c < 4; c++) {
                d[0][c] = dE0[c] + dO0[c];
                d[1][c] = dE1[c] + dO1[c];
            }

            // ---- epilogue: gate exchange, nonlinearity, stage h ----
#pragma unroll
            for (int nt = 0; nt < 2; nt++) {
                float p0 = __shfl_xor_sync(0xffffffffu, d[nt][0], 1);
                float p1 = __shfl_xor_sync(0xffffffffu, d[nt][1], 1);
                float p2 = __shfl_xor_sync(0xffffffffu, d[nt][2], 1);
                float p3 = __shfl_xor_sync(0xffffffffu, d[nt][3], 1);
                float gi, gf, gg, go;
                if (!odd) { gi = d[nt][0]; gf = d[nt][1]; gg = p0;       go = p1; }
                else      { gi = p2;       gf = p3;       gg = d[nt][2]; go = d[nt][3]; }

                __nv_bfloat162 xlo = *(__nv_bfloat162*)&xu[grp][nt].x;
                __nv_bfloat162 xhi = *(__nv_bfloat162*)&xu[grp][nt].y;
                float2 f0 = __bfloat1622float2(xlo);
                float2 f1 = __bfloat1622float2(xhi);
                gi += f0.x; gf += f0.y; gg += f1.x; go += f1.y;

                float i_ = siga(gi), f_ = siga(gf), g_ = tanha(gg), o_ = siga(go);
                float c = f_ * cst[grp][nt] + i_ * g_;
                cst[grp][nt] = c;
                float h = o_ * tanha(c);

                int jjloc = (wn * 2 + nt) * 2 + (tig >> 1);
                int kc = jjloc >> 3, tg2 = (jjloc & 7) >> 1, lo = jjloc & 1;
                __nv_bfloat16 hb = __float2bfloat16_rn(h);
                ((unsigned short*)&Hstage[wm * 32 + g * 4 + tg2])
                    [(odd + 2 * kc) * 2 + lo] = *(unsigned short*)&hb;

                int jc = j0 + jjloc;
                if (store_hs)    g_hsb[((size_t)b * Tz + t) * Hz + jc] = hb;
                if (t == Tz - 1) g_hlast[b * Hz + jc] = h;
            }

            // ---- publish: coalesced STG.128, then release flag ----
            __syncthreads();
            if (tid < 64) {
                int w = tid >> 5, l = tid & 31;
                bufW[(w * 32 + ct) * 32 + l] = Hstage[w * 32 + l];
            }
            __syncthreads();
            if (tid == 0) {
                asm volatile("st.release.gpu.global.u32 [%0], %1;"
                             :: "l"(flags + ct), "r"((unsigned)(t + 1)) : "memory");
            }
        }
    }
}

// ---------------------------------------------------------------------------
__global__ void head_kernel(const float* __restrict__ fc_w,
                            const float* __restrict__ fc_b,
                            const float* __restrict__ fc2_w,
                            const float* __restrict__ fc2_b,
                            float* __restrict__ out)
{
    int b = blockIdx.x;
    int f = threadIdx.x;
    const float* hb = &g_hlast[b * Hz];
    float s = 0.0f;
    for (int k = 0; k < Hz; k += 4) {
        float4 hv = *(const float4*)&hb[k];
        float4 wv = *(const float4*)&fc_w[(size_t)f * Hz + k];
        s = fmaf(hv.x, wv.x, s);
        s = fmaf(hv.y, wv.y, s);
        s = fmaf(hv.z, wv.z, s);
        s = fmaf(hv.w, wv.w, s);
    }
    s += fc_b[f];
    s = fmaxf(s, 0.0f);
    float v = s * fc2_w[f];

    __shared__ float red[64];
    red[f] = v;
    __syncthreads();
    if (f == 0) {
        float z = 0.0f;
#pragma unroll
        for (int i = 0; i < 64; i++) z += red[i];
        z += fc2_b[0];
        out[b] = 1.0f / (1.0f + expf(-z));
    }
}

// ---------------------------------------------------------------------------
extern "C" void kernel_launch(void* const* d_in, const int* in_sizes, int n_in,
                              void* d_out, int out_size)
{
    const float* x      = (const float*)d_in[0];
    const float* w_ih0  = (const float*)d_in[2];
    const float* w_hh0  = (const float*)d_in[3];
    const float* b_ih0  = (const float*)d_in[4];
    const float* b_hh0  = (const float*)d_in[5];
    const float* w_ih1  = (const float*)d_in[6];
    const float* w_hh1  = (const float*)d_in[7];
    const float* b_ih1  = (const float*)d_in[8];
    const float* b_hh1  = (const float*)d_in[9];
    const float* fc_w   = (const float*)d_in[10];
    const float* fc_b   = (const float*)d_in[11];
    const float* fc2_w  = (const float*)d_in[12];
    const float* fc2_b  = (const float*)d_in[13];
    float* out = (float*)d_out;

    static int smem_set = 0;
    if (!smem_set) {
        cudaFuncSetAttribute(lstm_seq2,
                             cudaFuncAttributeMaxDynamicSharedMemorySize, 66560);
        smem_set = 1;
    }

    __nv_bfloat16 *d_xb, *d_wb, *d_hsb;
    cudaGetSymbolAddress((void**)&d_xb,  g_xb);
    cudaGetSymbolAddress((void**)&d_wb,  g_wb);
    cudaGetSymbolAddress((void**)&d_hsb, g_hsb);

    dim3 ggrid(G4 / 64, (Bz * Tz) / 128);   // (32, 1024)
    int nz = (2 * 4 * 8192 + 4 * 32 + 255) / 256;

    // ---- pre-convert x (fp32 -> bf16) ----
    conv_bf16_kernel<<<(Bz * Tz * INz / 4 + 255) / 256, 256>>>(x, d_xb, Bz * Tz * INz / 4);

    // Layer 0
    conv_bf16_kernel<<<(G4 * INz / 4 + 255) / 256, 256>>>(w_ih0, d_wb, G4 * INz / 4);
    zero_state_kernel<<<nz, 256>>>();
    gemm_bf16_kernel<INz><<<ggrid, 256>>>(d_xb, b_ih0, b_hh0);
    lstm_seq2<<<64, 256, 66560>>>(w_hh0, 1);

    // Layer 1
    conv_bf16_kernel<<<(G4 * Hz / 4 + 255) / 256, 256>>>(w_ih1, d_wb, G4 * Hz / 4);
    zero_state_kernel<<<nz, 256>>>();
    gemm_bf16_kernel<Hz><<<ggrid, 256>>>(d_hsb, b_ih1, b_hh1);
    lstm_seq2<<<64, 256, 66560>>>(w_hh1, 0);

    // FC head
    head_kernel<<<Bz, 64>>>(fc_w, fc_b, fc2_w, fc2_b, out);
}

// round 13
// speedup vs baseline: 1.0056x; 1.0056x over previous
#include <cuda_runtime.h>
#include <cuda_bf16.h>
#include <math.h>
#include <stdint.h>

#define Bz   128
#define Tz   1024
#define INz  256
#define Hz   512
#define G4   2048   // 4*H

// ---------------- scratch (device globals) ---------------------------------
__device__ __nv_bfloat16 g_xgb[(size_t)Bz * Tz * G4];   // gate preacts, bf16, PERMUTED cols
__device__ __nv_bfloat16 g_hsb[(size_t)Bz * Tz * Hz];   // layer-0 hidden outputs, bf16 plain
__device__ __nv_bfloat16 g_xb[(size_t)Bz * Tz * INz];   // x pre-converted to bf16
__device__ __nv_bfloat16 g_wb[G4 * Hz];                 // W_ih pre-converted to bf16
__device__ unsigned g_phb[2][4][8192];                  // h exchange, bf16 A-frag layout
__device__ float g_hlast[Bz * Hz];                      // final h of running layer
__device__ unsigned g_flag[4][32];                      // per-CTA progress flags

// ---------------------------------------------------------------------------
__device__ __forceinline__ void mma_bf16(float* d, const uint4& a, unsigned b0, unsigned b1) {
    asm volatile(
        "mma.sync.aligned.m16n8k16.row.col.f32.bf16.bf16.f32 "
        "{%0,%1,%2,%3}, {%4,%5,%6,%7}, {%8,%9}, {%0,%1,%2,%3};\n"
        : "+f"(d[0]), "+f"(d[1]), "+f"(d[2]), "+f"(d[3])
        : "r"(a.x), "r"(a.y), "r"(a.z), "r"(a.w), "r"(b0), "r"(b1));
}
__device__ __forceinline__ float tanha(float x) {
    float y; asm("tanh.approx.f32 %0, %1;" : "=f"(y) : "f"(x)); return y;
}
__device__ __forceinline__ float siga(float x) { return 0.5f * tanha(0.5f * x) + 0.5f; }
__device__ __forceinline__ unsigned pack_bf16x2(float x, float y) {
    __nv_bfloat162 v = __floats2bfloat162_rn(x, y);
    return *(unsigned*)&v;
}

// ---------------------------------------------------------------------------
__global__ void zero_state_kernel() {
    int i = blockIdx.x * blockDim.x + threadIdx.x;
    if (i < 2 * 4 * 8192) ((unsigned*)g_phb)[i] = 0u;
    else if (i < 2 * 4 * 8192 + 4 * 32) ((unsigned*)g_flag)[i - 2 * 4 * 8192] = 0u;
}

// fp32 -> bf16 bulk convert (4 elts/thread)
__global__ void conv_bf16_kernel(const float* __restrict__ src,
                                 __nv_bfloat16* __restrict__ dst, int n4) {
    int i = blockIdx.x * blockDim.x + threadIdx.x;
    if (i < n4) {
        float4 v = *(const float4*)(src + (size_t)i * 4);
        uint2 o;
        o.x = pack_bf16x2(v.x, v.y);
        o.y = pack_bf16x2(v.z, v.w);
        *(uint2*)(dst + (size_t)i * 4) = o;
    }
}

// ---------------------------------------------------------------------------
// Input GEMM, bf16 m16n8k16, bf16 A and B sources, bf16 output.
// BM=128, BN=64, BK=32, 256 thr (4m x 2n warps). Permuted gate-col output.
// ---------------------------------------------------------------------------
template <int K>
__global__ void __launch_bounds__(256) gemm_bf16_kernel(
    const __nv_bfloat16* __restrict__ Xb,
    const float* __restrict__ b1, const float* __restrict__ b2)
{
    __shared__ uint4 Abuf[8][2][32];   // [m16][k16 step][lane] 8KB
    __shared__ uint2 Bbuf[8][2][32];   // [n8][k16 step][lane]  2KB
    __shared__ float sbias[64];

    int tid = threadIdx.x, lane = tid & 31, warp = tid >> 5;
    int wm = warp & 3, wn = warp >> 2;
    int g = lane >> 2, tig = lane & 3;
    size_t m0g = (size_t)blockIdx.y * 128;
    int    n0g = blockIdx.x * 64;

    if (tid < 64) {
        int ng  = n0g + tid;
        int row = (ng & 3) * Hz + (ng >> 2);
        sbias[tid] = b1[row] + b2[row];
    }

    float d[2][4][4];
#pragma unroll
    for (int a = 0; a < 2; a++)
#pragma unroll
        for (int b = 0; b < 4; b++)
#pragma unroll
            for (int c = 0; c < 4; c++) d[a][b][c] = 0.0f;

    for (int kb = 0; kb < K; kb += 32) {
        // ---- A fill: 4 quads/thread ----
#pragma unroll
        for (int i = 0; i < 4; i++) {
            int f4 = tid * 4 + i;
            int m = f4 >> 3, q = f4 & 7;
            uint2 u = *(const uint2*)&Xb[(m0g + m) * K + kb + q * 4];
            int mt = m >> 4, gg = m & 7, odd = (m >> 3) & 1;
            int ks = q >> 2, kc = (q >> 1) & 1, tg2 = (q & 1) * 2;
            int e = odd + 2 * kc;
            ((unsigned*)&Abuf[mt][ks][gg * 4 + tg2])[e]     = u.x;
            ((unsigned*)&Abuf[mt][ks][gg * 4 + tg2 + 1])[e] = u.y;
        }
        // ---- B fill: 2 quads/thread (from pre-converted bf16 W) ----
#pragma unroll
        for (int i = 0; i < 2; i++) {
            int fb = tid * 2 + i;
            int n = fb >> 3, q = fb & 7;
            int row = ((n0g + n) & 3) * Hz + ((n0g + n) >> 2);
            uint2 u = *(const uint2*)&g_wb[(size_t)row * K + kb + q * 4];
            int nt = n >> 3, gb = n & 7;
            int ks = q >> 2, r = (q >> 1) & 1, tg = (q & 1) * 2;
            ((unsigned*)&Bbuf[nt][ks][gb * 4 + tg])[r]     = u.x;
            ((unsigned*)&Bbuf[nt][ks][gb * 4 + tg + 1])[r] = u.y;
        }
        __syncthreads();
#pragma unroll
        for (int ks = 0; ks < 2; ks++) {
            uint4 a0 = Abuf[wm * 2 + 0][ks][lane];
            uint4 a1 = Abuf[wm * 2 + 1][ks][lane];
#pragma unroll
            for (int j = 0; j < 4; j++) {
                uint2 bb = Bbuf[wn * 4 + j][ks][lane];
                mma_bf16(d[0][j], a0, bb.x, bb.y);
                mma_bf16(d[1][j], a1, bb.x, bb.y);
            }
        }
        __syncthreads();
    }

    // ---- epilogue: add bias, store bf16 permuted ----
#pragma unroll
    for (int mt = 0; mt < 2; mt++) {
#pragma unroll
        for (int j = 0; j < 4; j++) {
            int col = wn * 32 + j * 8 + 2 * tig;
            float bi0 = sbias[col], bi1 = sbias[col + 1];
            size_t m = m0g + wm * 32 + mt * 16 + g;
            unsigned v0 = pack_bf16x2(d[mt][j][0] + bi0, d[mt][j][1] + bi1);
            unsigned v1 = pack_bf16x2(d[mt][j][2] + bi0, d[mt][j][3] + bi1);
            *(unsigned*)&g_xgb[m * G4 + n0g + col]       = v0;
            *(unsigned*)&g_xgb[(m + 8) * G4 + n0g + col] = v1;
        }
    }
}

// ---------------------------------------------------------------------------
// Persistent recurrent kernel: 64 CTAs, each handles ONE col tile (16 hid
// cols) for TWO independent batch groups, interleaved. The second group's
// compute hides the first group's flag/L2 round-trip latency.
// W_hh fragments in registers (shared across both groups).
// Dynamic smem: Hsm 2x32KB + Hstage 1KB = 66.5 KB.
// ---------------------------------------------------------------------------
__global__ void __launch_bounds__(256, 1) lstm_seq2(
    const float* __restrict__ w_hh, int store_hs)
{
    extern __shared__ unsigned char smraw[];
    uint4* HsmB   = (uint4*)smraw;          // [grp(2)][mt(2)][ks(32)][lane(32)]
    uint4* Hstage = HsmB + 4096;            // [mt(2)][lane(32)]

    int tid = threadIdx.x, lane = tid & 31, warp = tid >> 5;
    int wm = warp & 1, wn = warp >> 1;
    int g = lane >> 2, tig = lane & 3;
    int ct = blockIdx.x & 31, pp = blockIdx.x >> 5;   // col tile, group pair
    int j0 = ct * 16;
    int bt0 = pp * 2;
    int odd = tig & 1;
    int rl  = wm * 16 + g + 8 * odd;

    // ---- W_hh fragments into registers (held for all 1024 steps) ----
    unsigned wreg[2][32][2];
#pragma unroll
    for (int nt = 0; nt < 2; nt++) {
        int nl  = (wn * 2 + nt) * 8 + g;
        int row = (nl & 3) * Hz + j0 + (nl >> 2);
        const float* wr = &w_hh[(size_t)row * Hz];
#pragma unroll
        for (int ks = 0; ks < 32; ks++) {
#pragma unroll
            for (int r = 0; r < 2; r++) {
                float2 wv = *(const float2*)&wr[ks * 16 + 8 * r + 2 * tig];
                wreg[nt][ks][r] = pack_bf16x2(wv.x, wv.y);
            }
        }
    }

    float cst[2][2] = {{0.0f, 0.0f}, {0.0f, 0.0f}};

#pragma unroll 1
    for (int t = 0; t < Tz; t++) {
        // ---- prefetch xg (bf16) for both groups ----
        uint2 xu[2][2];
#pragma unroll
        for (int grp = 0; grp < 2; grp++) {
            int b = (bt0 + grp) * 32 + rl;
#pragma unroll
            for (int nt = 0; nt < 2; nt++) {
                int jjloc = (wn * 2 + nt) * 2 + (tig >> 1);
                xu[grp][nt] = __ldcs((const uint2*)
                    &g_xgb[((size_t)b * Tz + t) * G4 + ct * 64 + jjloc * 4]);
            }
        }

#pragma unroll 1
        for (int grp = 0; grp < 2; grp++) {
            int bt = bt0 + grp;
            int b  = bt * 32 + rl;
            unsigned* flags = &g_flag[bt][0];
            uint4* bufR = (uint4*)&g_phb[t & 1][bt][0];
            uint4* bufW = (uint4*)&g_phb[(t & 1) ^ 1][bt][0];
            uint4* Hsm  = HsmB + grp * 2048;

            // ---- wait: all 32 CTAs of this group finished step t-1 ----
            if (warp == 0) {
                unsigned v;
                do {
                    asm volatile("ld.acquire.gpu.global.u32 %0, [%1];"
                                 : "=r"(v) : "l"(flags + lane) : "memory");
                } while (!__all_sync(0xffffffffu, (int)(v >= (unsigned)t)));
            }
            __syncthreads();

            // ---- copy h tile (frag layout): global -> smem ----
#pragma unroll
            for (int i = 0; i < 8; i++) {
                int idx = i * 256 + tid;
                Hsm[idx] = __ldcg(&bufR[idx]);
            }
            __syncthreads();

            // ---- mma: 4 accumulator chains (ks parity x nt) ----
            float dE0[4] = {0, 0, 0, 0}, dO0[4] = {0, 0, 0, 0};
            float dE1[4] = {0, 0, 0, 0}, dO1[4] = {0, 0, 0, 0};
#pragma unroll
            for (int ks = 0; ks < 32; ks += 2) {
                uint4 a0 = Hsm[(wm * 32 + ks) * 32 + lane];
                uint4 a1 = Hsm[(wm * 32 + ks + 1) * 32 + lane];
                mma_bf16(dE0, a0, wreg[0][ks][0],     wreg[0][ks][1]);
                mma_bf16(dE1, a0, wreg[1][ks][0],     wreg[1][ks][1]);
                mma_bf16(dO0, a1, wreg[0][ks + 1][0], wreg[0][ks + 1][1]);
                mma_bf16(dO1, a1, wreg[1][ks + 1][0], wreg[1][ks + 1][1]);
            }
            float d[2][4];
#pragma unroll
            for (int c = 0; c < 4; c++) {
                d[0][c] = dE0[c] + dO0[c];
                d[1][c] = dE1[c] + dO1[c];
            }

            // ---- epilogue: gate exchange, nonlinearity, stage h ----
#pragma unroll
            for (int nt = 0; nt < 2; nt++) {
                float p0 = __shfl_xor_sync(0xffffffffu, d[nt][0], 1);
                float p1 = __shfl_xor_sync(0xffffffffu, d[nt][1], 1);
                float p2 = __shfl_xor_sync(0xffffffffu, d[nt][2], 1);
                float p3 = __shfl_xor_sync(0xffffffffu, d[nt][3], 1);
                float gi, gf, gg, go;
                if (!odd) { gi = d[nt][0]; gf = d[nt][1]; gg = p0;       go = p1; }
                else      { gi = p2;       gf = p3;       gg = d[nt][2]; go = d[nt][3]; }

                __nv_bfloat162 xlo = *(__nv_bfloat162*)&xu[grp][nt].x;
                __nv_bfloat162 xhi = *(__nv_bfloat162*)&xu[grp][nt].y;
                float2 f0 = __bfloat1622float2(xlo);
                float2 f1 = __bfloat1622float2(xhi);
                gi += f0.x; gf += f0.y; gg += f1.x; go += f1.y;

                float i_ = siga(gi), f_ = siga(gf), g_ = tanha(gg), o_ = siga(go);
                float c = f_ * cst[grp][nt] + i_ * g_;
                cst[grp][nt] = c;
                float h = o_ * tanha(c);

                int jjloc = (wn * 2 + nt) * 2 + (tig >> 1);
                int kc = jjloc >> 3, tg2 = (jjloc & 7) >> 1, lo = jjloc & 1;
                __nv_bfloat16 hb = __float2bfloat16_rn(h);
                ((unsigned short*)&Hstage[wm * 32 + g * 4 + tg2])
                    [(odd + 2 * kc) * 2 + lo] = *(unsigned short*)&hb;

                int jc = j0 + jjloc;
                if (store_hs)    g_hsb[((size_t)b * Tz + t) * Hz + jc] = hb;
                if (t == Tz - 1) g_hlast[b * Hz + jc] = h;
            }

            // ---- publish: coalesced STG.128, then release flag ----
            __syncthreads();
            if (tid < 64) {
                int w = tid >> 5, l = tid & 31;
                bufW[(w * 32 + ct) * 32 + l] = Hstage[w * 32 + l];
            }
            __syncthreads();
            if (tid == 0) {
                asm volatile("st.release.gpu.global.u32 [%0], %1;"
                             :: "l"(flags + ct), "r"((unsigned)(t + 1)) : "memory");
            }
        }
    }
}

// ---------------------------------------------------------------------------
__global__ void head_kernel(const float* __restrict__ fc_w,
                            const float* __restrict__ fc_b,
                            const float* __restrict__ fc2_w,
                            const float* __restrict__ fc2_b,
                            float* __restrict__ out)
{
    int b = blockIdx.x;
    int f = threadIdx.x;
    const float* hb = &g_hlast[b * Hz];
    float s = 0.0f;
    for (int k = 0; k < Hz; k += 4) {
        float4 hv = *(const float4*)&hb[k];
        float4 wv = *(const float4*)&fc_w[(size_t)f * Hz + k];
        s = fmaf(hv.x, wv.x, s);
        s = fmaf(hv.y, wv.y, s);
        s = fmaf(hv.z, wv.z, s);
        s = fmaf(hv.w, wv.w, s);
    }
    s += fc_b[f];
    s = fmaxf(s, 0.0f);
    float v = s * fc2_w[f];

    __shared__ float red[64];
    red[f] = v;
    __syncthreads();
    if (f == 0) {
        float z = 0.0f;
#pragma unroll
        for (int i = 0; i < 64; i++) z += red[i];
        z += fc2_b[0];
        out[b] = 1.0f / (1.0f + expf(-z));
    }
}

// ---------------------------------------------------------------------------
extern "C" void kernel_launch(void* const* d_in, const int* in_sizes, int n_in,
                              void* d_out, int out_size)
{
    const float* x      = (const float*)d_in[0];
    const float* w_ih0  = (const float*)d_in[2];
    const float* w_hh0  = (const float*)d_in[3];
    const float* b_ih0  = (const float*)d_in[4];
    const float* b_hh0  = (const float*)d_in[5];
    const float* w_ih1  = (const float*)d_in[6];
    const float* w_hh1  = (const float*)d_in[7];
    const float* b_ih1  = (const float*)d_in[8];
    const float* b_hh1  = (const float*)d_in[9];
    const float* fc_w   = (const float*)d_in[10];
    const float* fc_b   = (const float*)d_in[11];
    const float* fc2_w  = (const float*)d_in[12];
    const float* fc2_b  = (const float*)d_in[13];
    float* out = (float*)d_out;

    static int smem_set = 0;
    if (!smem_set) {
        cudaFuncSetAttribute(lstm_seq2,
                             cudaFuncAttributeMaxDynamicSharedMemorySize, 66560);
        smem_set = 1;
    }

    __nv_bfloat16 *d_xb, *d_wb, *d_hsb;
    cudaGetSymbolAddress((void**)&d_xb,  g_xb);
    cudaGetSymbolAddress((void**)&d_wb,  g_wb);
    cudaGetSymbolAddress((void**)&d_hsb, g_hsb);

    dim3 ggrid(G4 / 64, (Bz * Tz) / 128);   // (32, 1024)
    int nz = (2 * 4 * 8192 + 4 * 32 + 255) / 256;

    // ---- pre-convert x (fp32 -> bf16) ----
    conv_bf16_kernel<<<(Bz * Tz * INz / 4 + 255) / 256, 256>>>(x, d_xb, Bz * Tz * INz / 4);

    // Layer 0
    conv_bf16_kernel<<<(G4 * INz / 4 + 255) / 256, 256>>>(w_ih0, d_wb, G4 * INz / 4);
    zero_state_kernel<<<nz, 256>>>();
    gemm_bf16_kernel<INz><<<ggrid, 256>>>(d_xb, b_ih0, b_hh0);
    lstm_seq2<<<64, 256, 66560>>>(w_hh0, 1);

    // Layer 1
    conv_bf16_kernel<<<(G4 * Hz / 4 + 255) / 256, 256>>>(w_ih1, d_wb, G4 * Hz / 4);
    zero_state_kernel<<<nz, 256>>>();
    gemm_bf16_kernel<Hz><<<ggrid, 256>>>(d_hsb, b_ih1, b_hh1);
    lstm_seq2<<<64, 256, 66560>>>(w_hh1, 0);

    // FC head
    head_kernel<<<Bz, 64>>>(fc_w, fc_b, fc2_w, fc2_b, out);
}